// round 5
// baseline (speedup 1.0000x reference)
#include <cuda_runtime.h>
#include <math.h>

#define D       2048
#define NROWS   65536
#define NDREAMS 4
#define KMEM    8
#define MCAND   12

#define MV_BLOCKS 128            // Wq + Wg1: 64 blocks each, 64 rows per block
#define SIMS_BLOCKS 1024
#define K1_GRID (MV_BLOCKS + NDREAMS + SIMS_BLOCKS)

#define WC_BLOCKS 512            // 512 blocks x 8 warps = 4096 half-rows
#define K2_GRID (WC_BLOCKS + 1 + KMEM)

#define WM_BLOCKS 256            // 256 blocks x 8 rows
#define K3_GRID (1 + WM_BLOCKS)  // block 0 = logits/softmax

// ---------------- scratch (zero-initialized at module load; reset each launch) ----
__device__ float g_qv_pre[D];        // reset by K3 out-block
__device__ float g_gate_pre[D];      // reset by K3 out-block
__device__ float g_v[D];             // reset by K3 out-block
__device__ float g_spre[D];          // reset by K3 out-block
__device__ float g_C[MCAND * D];
__device__ float g_attn[MCAND];
__device__ float g_scalars[2];       // [0]=gate, [1]=cb
__device__ int   g_idx[KMEM];
__device__ float g_pool_v[SIMS_BLOCKS * KMEM];
__device__ int   g_pool_i[SIMS_BLOCKS * KMEM];
__device__ int   cnt_sims;           // reset by K1 last sims block
__device__ int   g_flag;             // attn ready; reset by K3 out-block
__device__ int   cnt_w;              // Wm completion; reset by K3 out-block

__device__ __forceinline__ float warp_sum(float v) {
#pragma unroll
    for (int off = 16; off; off >>= 1) v += __shfl_down_sync(0xFFFFFFFFu, v, off);
    return v;
}

// ======================= K1: bulk (matvecs + dreams + sims + top-8) ==========
__global__ __launch_bounds__(256) void k1_bulk(const float* __restrict__ z,
                                               const float* __restrict__ h,
                                               const float* __restrict__ mem,
                                               const float* __restrict__ Wq,
                                               const float* __restrict__ Wg1,
                                               const float* __restrict__ noise) {
    __shared__ float zsh[D];
    __shared__ float sscore[64];
    __shared__ float pv2[64];
    __shared__ int   pi2[64];
    __shared__ int   slast;
    int b = blockIdx.x, t = threadIdx.x;
    int warp = t >> 5, lane = t & 31;

    if (b < MV_BLOCKS) {
        const float* W   = (b < 64) ? Wq : Wg1;
        float*       dst = (b < 64) ? g_qv_pre : g_gate_pre;
        int rb = (b & 63) * 64;
        float acc[8];
#pragma unroll
        for (int k = 0; k < 8; ++k) acc[k] = 0.f;
        for (int i = 0; i < 64; ++i) {
            int row = rb + i;
            float x = (row < D) ? z[row] : h[row - D];
            const float* wr = W + (size_t)row * D;
#pragma unroll
            for (int k = 0; k < 8; ++k) acc[k] += x * wr[t + 256 * k];
        }
#pragma unroll
        for (int k = 0; k < 8; ++k) atomicAdd(&dst[t + 256 * k], acc[k]);
    } else if (b < MV_BLOCKS + NDREAMS) {
        __shared__ float red[8];
        int dm = b - MV_BLOCKS;
        float ss = 0.f;
#pragma unroll
        for (int k = 0; k < 8; ++k) {
            int j = t + 256 * k;
            float v = 0.7f * noise[dm * D + j] + 0.3f * z[j];
            zsh[j] = v;
            ss += v * v;
        }
        ss = warp_sum(ss);
        if (lane == 0) red[warp] = ss;
        __syncthreads();
        if (t == 0) {
            float s = 0.f;
#pragma unroll
            for (int w = 0; w < 8; ++w) s += red[w];
            red[0] = s;
        }
        __syncthreads();
        float inv = 1.0f / fmaxf(sqrtf(red[0]), 1e-12f);
#pragma unroll
        for (int k = 0; k < 8; ++k) {
            int j = t + 256 * k;
            g_C[(KMEM + dm) * D + j] = zsh[j] * inv;
        }
    } else {
        int sb = b - MV_BLOCKS - NDREAMS;            // 0..1023
#pragma unroll
        for (int k = 0; k < 8; ++k) zsh[t + 256 * k] = z[t + 256 * k];
        __syncthreads();
        const float4* z4 = (const float4*)zsh;
        int wg = sb * 8 + warp;                      // 0..8191
#pragma unroll 1
        for (int p = 0; p < 4; ++p) {
            int rA = 2 * wg + 16384 * p;
            const float4* A4 = (const float4*)(mem + (size_t)rA * D);
            const float4* B4 = (const float4*)(mem + (size_t)(rA + 1) * D);
            float da0 = 0, da1 = 0, da2 = 0, da3 = 0;
            float na0 = 0, na1 = 0, na2 = 0, na3 = 0;
            float db0 = 0, db1 = 0, db2 = 0, db3 = 0;
            float nb0 = 0, nb1 = 0, nb2 = 0, nb3 = 0;
#pragma unroll
            for (int it = 0; it < 16; ++it) {
                float4 va = A4[lane + 32 * it];
                float4 vb = B4[lane + 32 * it];
                float4 zz = z4[lane + 32 * it];
                da0 += va.x * zz.x; da1 += va.y * zz.y; da2 += va.z * zz.z; da3 += va.w * zz.w;
                na0 += va.x * va.x; na1 += va.y * va.y; na2 += va.z * va.z; na3 += va.w * va.w;
                db0 += vb.x * zz.x; db1 += vb.y * zz.y; db2 += vb.z * zz.z; db3 += vb.w * zz.w;
                nb0 += vb.x * vb.x; nb1 += vb.y * vb.y; nb2 += vb.z * vb.z; nb3 += vb.w * vb.w;
            }
            float dA = warp_sum((da0 + da1) + (da2 + da3));
            float nA = warp_sum((na0 + na1) + (na2 + na3));
            float dB = warp_sum((db0 + db1) + (db2 + db3));
            float nB = warp_sum((nb0 + nb1) + (nb2 + nb3));
            if (lane == 0) {
                sscore[warp * 8 + p * 2]     = dA * rsqrtf(nA);
                sscore[warp * 8 + p * 2 + 1] = dB * rsqrtf(nB);
            }
        }
        __syncthreads();

        // ---- block top-8 over the 64 scores (warp 0) ----
        if (warp == 0) {
            int s0 = lane, s1 = lane + 32;
            float v0 = sscore[s0], v1 = sscore[s1];
            int r0 = 2 * (sb * 8 + (s0 >> 3)) + 16384 * ((s0 & 7) >> 1) + (s0 & 1);
            int r1 = 2 * (sb * 8 + (s1 >> 3)) + 16384 * ((s1 & 7) >> 1) + (s1 & 1);
            if (v1 > v0) { float tv = v0; v0 = v1; v1 = tv; int ti = r0; r0 = r1; r1 = ti; }
#pragma unroll 1
            for (int p = 0; p < KMEM; ++p) {
                float best = v0; int bl = lane;
#pragma unroll
                for (int off = 16; off; off >>= 1) {
                    float ov = __shfl_down_sync(0xFFFFFFFFu, best, off);
                    int obl  = __shfl_down_sync(0xFFFFFFFFu, bl, off);
                    if (ov > best) { best = ov; bl = obl; }
                }
                int wl = __shfl_sync(0xFFFFFFFFu, bl, 0);
                float wv = __shfl_sync(0xFFFFFFFFu, v0, wl);
                int  wr = __shfl_sync(0xFFFFFFFFu, r0, wl);
                if (lane == 0) { g_pool_v[sb * 8 + p] = wv; g_pool_i[sb * 8 + p] = wr; }
                if (lane == wl) { v0 = v1; r0 = r1; v1 = -INFINITY; }
            }
        }
        __threadfence();
        __syncthreads();
        if (t == 0) slast = atomicAdd(&cnt_sims, 1);
        __syncthreads();
        if (slast == SIMS_BLOCKS - 1) {
            __threadfence();
            float bv[KMEM]; int bi[KMEM];
#pragma unroll
            for (int q = 0; q < KMEM; ++q) { bv[q] = -INFINITY; bi[q] = 0; }
#pragma unroll 1
            for (int f = 0; f < 32; ++f) {
                int e = t + 256 * f;
                float s = g_pool_v[e];
                if (s > bv[KMEM - 1]) {
                    bv[KMEM - 1] = s; bi[KMEM - 1] = g_pool_i[e];
#pragma unroll
                    for (int q = KMEM - 1; q > 0; --q) {
                        if (bv[q] > bv[q - 1]) {
                            float tv = bv[q - 1]; int ti = bi[q - 1];
                            bv[q - 1] = bv[q]; bi[q - 1] = bi[q];
                            bv[q] = tv; bi[q] = ti;
                        }
                    }
                }
            }
#pragma unroll 1
            for (int p = 0; p < KMEM; ++p) {
                float v = bv[0]; int id = bi[0]; int ln = lane;
#pragma unroll
                for (int off = 16; off; off >>= 1) {
                    float ov = __shfl_down_sync(0xFFFFFFFFu, v, off);
                    int oid  = __shfl_down_sync(0xFFFFFFFFu, id, off);
                    int oln  = __shfl_down_sync(0xFFFFFFFFu, ln, off);
                    if (ov > v) { v = ov; id = oid; ln = oln; }
                }
                int wln = __shfl_sync(0xFFFFFFFFu, ln, 0);
                if (lane == 0) { pv2[warp * 8 + p] = v; pi2[warp * 8 + p] = id; }
                if (lane == wln) {
#pragma unroll
                    for (int q = 0; q < KMEM - 1; ++q) { bv[q] = bv[q + 1]; bi[q] = bi[q + 1]; }
                    bv[KMEM - 1] = -INFINITY;
                }
            }
            __syncthreads();
            if (warp == 0) {
                float v0 = pv2[lane], v1 = pv2[lane + 32];
                int   i0 = pi2[lane], i1 = pi2[lane + 32];
                if (v1 > v0) { float tv = v0; v0 = v1; v1 = tv; int ti = i0; i0 = i1; i1 = ti; }
#pragma unroll 1
                for (int p = 0; p < KMEM; ++p) {
                    float best = v0; int bl = lane;
#pragma unroll
                    for (int off = 16; off; off >>= 1) {
                        float ov = __shfl_down_sync(0xFFFFFFFFu, best, off);
                        int obl  = __shfl_down_sync(0xFFFFFFFFu, bl, off);
                        if (ov > best) { best = ov; bl = obl; }
                    }
                    int wl = __shfl_sync(0xFFFFFFFFu, bl, 0);
                    int wi = __shfl_sync(0xFFFFFFFFu, i0, wl);
                    if (lane == 0) g_idx[p] = wi;
                    if (lane == wl) { v0 = v1; i0 = i1; v1 = -INFINITY; }
                }
                if (lane == 0) atomicExch(&cnt_sims, 0);
            }
        }
    }
}

// ======================= K2: Wc matvec + scalars + gather (all independent) ===
// blocks [0,512): Wc half-row matvec -> g_v (atomicAdd; g_v pre-zeroed)
// block 512     : scalars (cb, gate)
// blocks [513,521): gather protos -> g_C rows 0..7
__global__ __launch_bounds__(256) void k2_mid(const float* __restrict__ mem,
                                              const float* __restrict__ Wc,
                                              const float* __restrict__ bq,
                                              const float* __restrict__ ws,
                                              const float* __restrict__ bs,
                                              const float* __restrict__ bc,
                                              const float* __restrict__ bg1,
                                              const float* __restrict__ wg2,
                                              const float* __restrict__ bg2) {
    __shared__ float qsh[D];
    int b = blockIdx.x, t = threadIdx.x;
    int warp = t >> 5, lane = t & 31;

    if (b < WC_BLOCKS) {
#pragma unroll
        for (int k = 0; k < 8; ++k) {
            int j = t + 256 * k;
            qsh[j] = tanhf(g_qv_pre[j] + bq[j]) * ws[j];
        }
        __syncthreads();
        int w = b * 8 + warp;                 // 0..4095
        int row = w >> 1, half = w & 1;
        const float4* wr = (const float4*)(Wc + (size_t)row * D + half * (D / 2));
        const float4* q4 = (const float4*)(qsh + half * (D / 2));
        float a0 = 0, a1 = 0, a2 = 0, a3 = 0;
#pragma unroll
        for (int it = 0; it < 8; ++it) {
            float4 wv = wr[lane + 32 * it];
            float4 qv = q4[lane + 32 * it];
            a0 += wv.x * qv.x; a1 += wv.y * qv.y; a2 += wv.z * qv.z; a3 += wv.w * qv.w;
        }
        float s = warp_sum((a0 + a1) + (a2 + a3));
        if (lane == 0) atomicAdd(&g_v[row], s);
    } else if (b == WC_BLOCKS) {
        __shared__ float scb[8], sgp[8];
        float cbp = 0.f, gp = 0.f;
#pragma unroll
        for (int k = 0; k < 8; ++k) {
            int j = t + 256 * k;
            cbp += bc[j] * tanhf(g_qv_pre[j] + bq[j]) * ws[j];
            gp  += tanhf(g_gate_pre[j] + bg1[j]) * wg2[j];
        }
        cbp = warp_sum(cbp);
        gp  = warp_sum(gp);
        if (lane == 0) { scb[warp] = cbp; sgp[warp] = gp; }
        __syncthreads();
        if (t == 0) {
            float c = 0.f, g = 0.f;
#pragma unroll
            for (int w2 = 0; w2 < 8; ++w2) { c += scb[w2]; g += sgp[w2]; }
            g_scalars[1] = c + bs[0];
            g_scalars[0] = 1.0f / (1.0f + expf(-(g + bg2[0])));
        }
    } else {
        int m = b - WC_BLOCKS - 1;            // 0..7
        int r = g_idx[m];
        const float4* src = (const float4*)(mem + (size_t)r * D);
        float4* dst = (float4*)(g_C + m * D);
#pragma unroll
        for (int k = 0; k < 2; ++k) dst[t + 256 * k] = src[t + 256 * k];
    }
}

// ======================= K3: logits/softmax (block 0) + Wm + out ==============
// block 0        : logits = C@v + cb -> softmax -> g_attn ; flag release
// blocks [1,257) : poll flag (volatile loads), Wm rows 8(b-1)..+8 -> g_spre;
//                  last block (counter) writes out + resets all state.
__global__ __launch_bounds__(256) void k3_fin(const float* __restrict__ Wm,
                                              const float* __restrict__ bm,
                                              float* __restrict__ out) {
    __shared__ float wred[8][MCAND];
    __shared__ float sx[8];
    __shared__ int   smlast;
    int b = blockIdx.x, t = threadIdx.x;
    int warp = t >> 5, lane = t & 31;

    if (b == 0) {
        float part[MCAND];
#pragma unroll
        for (int m = 0; m < MCAND; ++m) part[m] = 0.f;
        for (int j = t; j < D; j += 256) {
            float vj = g_v[j];
#pragma unroll
            for (int m = 0; m < MCAND; ++m) part[m] += g_C[m * D + j] * vj;
        }
#pragma unroll
        for (int m = 0; m < MCAND; ++m) part[m] = warp_sum(part[m]);
        if (lane == 0) {
#pragma unroll
            for (int m = 0; m < MCAND; ++m) wred[warp][m] = part[m];
        }
        __syncthreads();
        if (t == 0) {
            float lg[MCAND]; float mx = -INFINITY;
            float cb = g_scalars[1];
#pragma unroll
            for (int m = 0; m < MCAND; ++m) {
                float s = cb;
                for (int w = 0; w < 8; ++w) s += wred[w][m];
                lg[m] = s;
                mx = fmaxf(mx, s);
            }
            float den = 0.f;
#pragma unroll
            for (int m = 0; m < MCAND; ++m) { lg[m] = expf(lg[m] - mx); den += lg[m]; }
            float inv = 1.0f / den;
#pragma unroll
            for (int m = 0; m < MCAND; ++m) g_attn[m] = lg[m] * inv;
            __threadfence();
            *(volatile int*)&g_flag = 1;
        }
    } else {
        int rb = (b - 1) * 8;
        // lightweight poll: plain volatile load, no atomic traffic
        if (t == 0) {
            volatile int* vf = &g_flag;
            while (*vf == 0) __nanosleep(64);
        }
        __syncthreads();
        __threadfence();
        if (t < 8) sx[t] = 0.f;
        __syncthreads();
        if (t < 8 * MCAND) {
            int i = t / MCAND, m = t - i * MCAND;
            atomicAdd(&sx[i], __ldcg(&g_attn[m]) * __ldcg(&g_C[m * D + rb + i]));
        }
        __syncthreads();
        float acc[8];
#pragma unroll
        for (int k = 0; k < 8; ++k) acc[k] = 0.f;
#pragma unroll
        for (int i = 0; i < 8; ++i) {
            float x = sx[i];
            const float* wr2 = Wm + (size_t)(rb + i) * D;
#pragma unroll
            for (int k = 0; k < 8; ++k) acc[k] += x * wr2[t + 256 * k];
        }
#pragma unroll
        for (int k = 0; k < 8; ++k) atomicAdd(&g_spre[t + 256 * k], acc[k]);
        __threadfence();
        __syncthreads();
        if (t == 0) smlast = atomicAdd(&cnt_w, 1);
        __syncthreads();
        if (smlast == WM_BLOCKS - 1) {
            __threadfence();
            float g = g_scalars[0];
#pragma unroll
            for (int k = 0; k < 8; ++k) {
                int j = t + 256 * k;
                out[j] = g * tanhf(__ldcg(&g_spre[j]) + bm[j]);
                g_spre[j] = 0.f;
                g_qv_pre[j] = 0.f;
                g_gate_pre[j] = 0.f;
                g_v[j] = 0.f;
            }
            if (t == 0) {
                atomicExch(&cnt_w, 0);
                atomicExch(&g_flag, 0);
            }
        }
    }
}

// ======================= launch =======================
extern "C" void kernel_launch(void* const* d_in, const int* in_sizes, int n_in,
                              void* d_out, int out_size) {
    const float* z     = (const float*)d_in[0];
    const float* h     = (const float*)d_in[1];
    const float* mem   = (const float*)d_in[2];
    const float* noise = (const float*)d_in[3];
    const float* Wq    = (const float*)d_in[4];
    const float* bq    = (const float*)d_in[5];
    const float* Wc    = (const float*)d_in[6];
    const float* bc    = (const float*)d_in[7];
    const float* ws    = (const float*)d_in[8];
    const float* bs    = (const float*)d_in[9];
    const float* Wm    = (const float*)d_in[10];
    const float* bm    = (const float*)d_in[11];
    const float* Wg1   = (const float*)d_in[12];
    const float* bg1   = (const float*)d_in[13];
    const float* wg2   = (const float*)d_in[14];
    const float* bg2   = (const float*)d_in[15];
    float* out = (float*)d_out;

    k1_bulk<<<K1_GRID, 256>>>(z, h, mem, Wq, Wg1, noise);
    k2_mid<<<K2_GRID, 256>>>(mem, Wc, bq, ws, bs, bc, bg1, wg2, bg2);
    k3_fin<<<K3_GRID, 256>>>(Wm, bm, out);
}

// round 6
// speedup vs baseline: 1.3963x; 1.3963x over previous
#include <cuda_runtime.h>
#include <math.h>

#define D       2048
#define NROWS   65536
#define NDREAMS 4
#define KMEM    8
#define MCAND   12

#define MV_BLOCKS 128            // Wq + Wg1: 64 blocks each, 64 rows per block
#define SIMS_BLOCKS 1024
#define K1_GRID (MV_BLOCKS + NDREAMS + SIMS_BLOCKS)

#define WC_BLOCKS 512            // 512 blocks x 8 warps = 4096 half-rows
#define K2_GRID (WC_BLOCKS + 2)  // + scalars block + select/gather block

#define WM_BLOCKS 256            // 256 blocks x 8 rows
#define K3_GRID (1 + WM_BLOCKS)

// ---------------- scratch (zero-initialized at module load; reset each launch) ----
__device__ float g_qv_pre[D];        // reset by K3 out-block
__device__ float g_gate_pre[D];      // reset by K3 out-block
__device__ float g_v[D];             // reset by K3 out-block
__device__ float g_spre[D];          // reset by K3 out-block
__device__ float g_C[MCAND * D];
__device__ float g_attn[MCAND];
__device__ float g_scalars[2];       // [0]=gate, [1]=cb
__device__ int   g_idx[KMEM];
__device__ float g_pool_v[SIMS_BLOCKS * KMEM];
__device__ int   g_pool_i[SIMS_BLOCKS * KMEM];
__device__ int   g_flag;             // attn ready; reset by K3 out-block
__device__ int   cnt_w;              // Wm completion; reset by K3 out-block

__device__ __forceinline__ float warp_sum(float v) {
#pragma unroll
    for (int off = 16; off; off >>= 1) v += __shfl_down_sync(0xFFFFFFFFu, v, off);
    return v;
}

// ======================= K1: bulk (matvecs + dreams + sims) ==================
// blocks [0,128)     : Wq / Wg1 matvec partials (atomicAdd)
// blocks [128,132)   : dreams -> g_C rows 8..11
// blocks [132,1156)  : cosine scores; block top-8 -> pool (final select in K2)
__global__ __launch_bounds__(256, 4) void k1_bulk(const float* __restrict__ z,
                                                  const float* __restrict__ h,
                                                  const float* __restrict__ mem,
                                                  const float* __restrict__ Wq,
                                                  const float* __restrict__ Wg1,
                                                  const float* __restrict__ noise) {
    __shared__ float zsh[D];
    __shared__ float sscore[64];
    int b = blockIdx.x, t = threadIdx.x;
    int warp = t >> 5, lane = t & 31;

    if (b < MV_BLOCKS) {
        const float* W   = (b < 64) ? Wq : Wg1;
        float*       dst = (b < 64) ? g_qv_pre : g_gate_pre;
        int rb = (b & 63) * 64;
        float acc[8];
#pragma unroll
        for (int k = 0; k < 8; ++k) acc[k] = 0.f;
        for (int i = 0; i < 64; ++i) {
            int row = rb + i;
            float x = (row < D) ? z[row] : h[row - D];
            const float* wr = W + (size_t)row * D;
#pragma unroll
            for (int k = 0; k < 8; ++k) acc[k] += x * wr[t + 256 * k];
        }
#pragma unroll
        for (int k = 0; k < 8; ++k) atomicAdd(&dst[t + 256 * k], acc[k]);
    } else if (b < MV_BLOCKS + NDREAMS) {
        __shared__ float red[8];
        int dm = b - MV_BLOCKS;
        float ss = 0.f;
#pragma unroll
        for (int k = 0; k < 8; ++k) {
            int j = t + 256 * k;
            float v = 0.7f * noise[dm * D + j] + 0.3f * z[j];
            zsh[j] = v;
            ss += v * v;
        }
        ss = warp_sum(ss);
        if (lane == 0) red[warp] = ss;
        __syncthreads();
        if (t == 0) {
            float s = 0.f;
#pragma unroll
            for (int w = 0; w < 8; ++w) s += red[w];
            red[0] = s;
        }
        __syncthreads();
        float inv = 1.0f / fmaxf(sqrtf(red[0]), 1e-12f);
#pragma unroll
        for (int k = 0; k < 8; ++k) {
            int j = t + 256 * k;
            g_C[(KMEM + dm) * D + j] = zsh[j] * inv;
        }
    } else {
        int sb = b - MV_BLOCKS - NDREAMS;            // 0..1023
#pragma unroll
        for (int k = 0; k < 8; ++k) zsh[t + 256 * k] = z[t + 256 * k];
        __syncthreads();
        const float4* z4 = (const float4*)zsh;
        int wg = sb * 8 + warp;                      // 0..8191
#pragma unroll 1
        for (int p = 0; p < 4; ++p) {
            int rA = 2 * wg + 16384 * p;
            const float4* A4 = (const float4*)(mem + (size_t)rA * D);
            const float4* B4 = (const float4*)(mem + (size_t)(rA + 1) * D);
            float dA0 = 0, dA1 = 0, nA0 = 0, nA1 = 0;
            float dB0 = 0, dB1 = 0, nB0 = 0, nB1 = 0;
#pragma unroll
            for (int it = 0; it < 16; ++it) {
                float4 va = __ldcs(&A4[lane + 32 * it]);
                float4 vb = __ldcs(&B4[lane + 32 * it]);
                float4 zz = z4[lane + 32 * it];
                dA0 += va.x * zz.x + va.y * zz.y;
                dA1 += va.z * zz.z + va.w * zz.w;
                nA0 += va.x * va.x + va.y * va.y;
                nA1 += va.z * va.z + va.w * va.w;
                dB0 += vb.x * zz.x + vb.y * zz.y;
                dB1 += vb.z * zz.z + vb.w * zz.w;
                nB0 += vb.x * vb.x + vb.y * vb.y;
                nB1 += vb.z * vb.z + vb.w * vb.w;
            }
            float dA = warp_sum(dA0 + dA1);
            float nA = warp_sum(nA0 + nA1);
            float dB = warp_sum(dB0 + dB1);
            float nB = warp_sum(nB0 + nB1);
            if (lane == 0) {
                sscore[warp * 8 + p * 2]     = dA * rsqrtf(nA);
                sscore[warp * 8 + p * 2 + 1] = dB * rsqrtf(nB);
            }
        }
        __syncthreads();

        // ---- block top-8 over the 64 scores (warp 0 only) ----
        if (warp == 0) {
            int s0 = lane, s1 = lane + 32;
            float v0 = sscore[s0], v1 = sscore[s1];
            int r0 = 2 * (sb * 8 + (s0 >> 3)) + 16384 * ((s0 & 7) >> 1) + (s0 & 1);
            int r1 = 2 * (sb * 8 + (s1 >> 3)) + 16384 * ((s1 & 7) >> 1) + (s1 & 1);
            if (v1 > v0) { float tv = v0; v0 = v1; v1 = tv; int ti = r0; r0 = r1; r1 = ti; }
#pragma unroll 1
            for (int p = 0; p < KMEM; ++p) {
                float best = v0; int bl = lane;
#pragma unroll
                for (int off = 16; off; off >>= 1) {
                    float ov = __shfl_down_sync(0xFFFFFFFFu, best, off);
                    int obl  = __shfl_down_sync(0xFFFFFFFFu, bl, off);
                    if (ov > best) { best = ov; bl = obl; }
                }
                int wl = __shfl_sync(0xFFFFFFFFu, bl, 0);
                float wv = __shfl_sync(0xFFFFFFFFu, v0, wl);
                int  wr = __shfl_sync(0xFFFFFFFFu, r0, wl);
                if (lane == 0) { g_pool_v[sb * 8 + p] = wv; g_pool_i[sb * 8 + p] = wr; }
                if (lane == wl) { v0 = v1; r0 = r1; v1 = -INFINITY; }
            }
        }
    }
}

// ======================= K2: Wc matvec + scalars + top-8 select/gather ========
// blocks [0,512)   : Wc half-row matvec -> g_v (atomicAdd; g_v pre-zeroed)
// block 512        : scalars (cb, gate)
// block 513        : final top-8 from pool -> g_idx, then gather protos -> g_C
__global__ __launch_bounds__(256) void k2_mid(const float* __restrict__ mem,
                                              const float* __restrict__ Wc,
                                              const float* __restrict__ bq,
                                              const float* __restrict__ ws,
                                              const float* __restrict__ bs,
                                              const float* __restrict__ bc,
                                              const float* __restrict__ bg1,
                                              const float* __restrict__ wg2,
                                              const float* __restrict__ bg2) {
    __shared__ float qsh[D];
    int b = blockIdx.x, t = threadIdx.x;
    int warp = t >> 5, lane = t & 31;

    if (b < WC_BLOCKS) {
#pragma unroll
        for (int k = 0; k < 8; ++k) {
            int j = t + 256 * k;
            qsh[j] = tanhf(g_qv_pre[j] + bq[j]) * ws[j];
        }
        __syncthreads();
        int w = b * 8 + warp;                 // 0..4095
        int row = w >> 1, half = w & 1;
        const float4* wr = (const float4*)(Wc + (size_t)row * D + half * (D / 2));
        const float4* q4 = (const float4*)(qsh + half * (D / 2));
        float a0 = 0, a1 = 0, a2 = 0, a3 = 0;
#pragma unroll
        for (int it = 0; it < 8; ++it) {
            float4 wv = wr[lane + 32 * it];
            float4 qv = q4[lane + 32 * it];
            a0 += wv.x * qv.x; a1 += wv.y * qv.y; a2 += wv.z * qv.z; a3 += wv.w * qv.w;
        }
        float s = warp_sum((a0 + a1) + (a2 + a3));
        if (lane == 0) atomicAdd(&g_v[row], s);
    } else if (b == WC_BLOCKS) {
        __shared__ float scb[8], sgp[8];
        float cbp = 0.f, gp = 0.f;
#pragma unroll
        for (int k = 0; k < 8; ++k) {
            int j = t + 256 * k;
            cbp += bc[j] * tanhf(g_qv_pre[j] + bq[j]) * ws[j];
            gp  += tanhf(g_gate_pre[j] + bg1[j]) * wg2[j];
        }
        cbp = warp_sum(cbp);
        gp  = warp_sum(gp);
        if (lane == 0) { scb[warp] = cbp; sgp[warp] = gp; }
        __syncthreads();
        if (t == 0) {
            float c = 0.f, g = 0.f;
#pragma unroll
            for (int w2 = 0; w2 < 8; ++w2) { c += scb[w2]; g += sgp[w2]; }
            g_scalars[1] = c + bs[0];
            g_scalars[0] = 1.0f / (1.0f + expf(-(g + bg2[0])));
        }
    } else {
        // ---- final top-8 over 8192-entry pool, then gather protos ----
        __shared__ float pv2[64];
        __shared__ int   pi2[64];
        __shared__ int   sidx[KMEM];
        float bv[KMEM]; int bi[KMEM];
#pragma unroll
        for (int q = 0; q < KMEM; ++q) { bv[q] = -INFINITY; bi[q] = 0; }
#pragma unroll 1
        for (int f = 0; f < 32; ++f) {
            int e = t + 256 * f;
            float s = g_pool_v[e];
            if (s > bv[KMEM - 1]) {
                bv[KMEM - 1] = s; bi[KMEM - 1] = g_pool_i[e];
#pragma unroll
                for (int q = KMEM - 1; q > 0; --q) {
                    if (bv[q] > bv[q - 1]) {
                        float tv = bv[q - 1]; int ti = bi[q - 1];
                        bv[q - 1] = bv[q]; bi[q - 1] = bi[q];
                        bv[q] = tv; bi[q] = ti;
                    }
                }
            }
        }
#pragma unroll 1
        for (int p = 0; p < KMEM; ++p) {
            float v = bv[0]; int id = bi[0]; int ln = lane;
#pragma unroll
            for (int off = 16; off; off >>= 1) {
                float ov = __shfl_down_sync(0xFFFFFFFFu, v, off);
                int oid  = __shfl_down_sync(0xFFFFFFFFu, id, off);
                int oln  = __shfl_down_sync(0xFFFFFFFFu, ln, off);
                if (ov > v) { v = ov; id = oid; ln = oln; }
            }
            int wln = __shfl_sync(0xFFFFFFFFu, ln, 0);
            if (lane == 0) { pv2[warp * 8 + p] = v; pi2[warp * 8 + p] = id; }
            if (lane == wln) {
#pragma unroll
                for (int q = 0; q < KMEM - 1; ++q) { bv[q] = bv[q + 1]; bi[q] = bi[q + 1]; }
                bv[KMEM - 1] = -INFINITY;
            }
        }
        __syncthreads();
        if (warp == 0) {
            float v0 = pv2[lane], v1 = pv2[lane + 32];
            int   i0 = pi2[lane], i1 = pi2[lane + 32];
            if (v1 > v0) { float tv = v0; v0 = v1; v1 = tv; int ti = i0; i0 = i1; i1 = ti; }
#pragma unroll 1
            for (int p = 0; p < KMEM; ++p) {
                float best = v0; int bl = lane;
#pragma unroll
                for (int off = 16; off; off >>= 1) {
                    float ov = __shfl_down_sync(0xFFFFFFFFu, best, off);
                    int obl  = __shfl_down_sync(0xFFFFFFFFu, bl, off);
                    if (ov > best) { best = ov; bl = obl; }
                }
                int wl = __shfl_sync(0xFFFFFFFFu, bl, 0);
                int wi = __shfl_sync(0xFFFFFFFFu, i0, wl);
                if (lane == 0) { g_idx[p] = wi; sidx[p] = wi; }
                if (lane == wl) { v0 = v1; i0 = i1; v1 = -INFINITY; }
            }
        }
        __syncthreads();
        // gather 8 protos (8 x 8KB) with all 256 threads
#pragma unroll 1
        for (int m = 0; m < KMEM; ++m) {
            int r = sidx[m];
            const float4* src = (const float4*)(mem + (size_t)r * D);
            float4* dst = (float4*)(g_C + m * D);
#pragma unroll
            for (int k = 0; k < 2; ++k) dst[t + 256 * k] = src[t + 256 * k];
        }
    }
}

// ======================= K3: logits/softmax (block 0) + Wm + out ==============
__global__ __launch_bounds__(256) void k3_fin(const float* __restrict__ Wm,
                                              const float* __restrict__ bm,
                                              float* __restrict__ out) {
    __shared__ float wred[8][MCAND];
    __shared__ float sx[8];
    __shared__ int   smlast;
    int b = blockIdx.x, t = threadIdx.x;
    int warp = t >> 5, lane = t & 31;

    if (b == 0) {
        float part[MCAND];
#pragma unroll
        for (int m = 0; m < MCAND; ++m) part[m] = 0.f;
        for (int j = t; j < D; j += 256) {
            float vj = g_v[j];
#pragma unroll
            for (int m = 0; m < MCAND; ++m) part[m] += g_C[m * D + j] * vj;
        }
#pragma unroll
        for (int m = 0; m < MCAND; ++m) part[m] = warp_sum(part[m]);
        if (lane == 0) {
#pragma unroll
            for (int m = 0; m < MCAND; ++m) wred[warp][m] = part[m];
        }
        __syncthreads();
        if (t == 0) {
            float lg[MCAND]; float mx = -INFINITY;
            float cb = g_scalars[1];
#pragma unroll
            for (int m = 0; m < MCAND; ++m) {
                float s = cb;
                for (int w = 0; w < 8; ++w) s += wred[w][m];
                lg[m] = s;
                mx = fmaxf(mx, s);
            }
            float den = 0.f;
#pragma unroll
            for (int m = 0; m < MCAND; ++m) { lg[m] = expf(lg[m] - mx); den += lg[m]; }
            float inv = 1.0f / den;
#pragma unroll
            for (int m = 0; m < MCAND; ++m) g_attn[m] = lg[m] * inv;
            __threadfence();
            *(volatile int*)&g_flag = 1;
        }
    } else {
        int rb = (b - 1) * 8;
        if (t == 0) {
            volatile int* vf = &g_flag;
            while (*vf == 0) __nanosleep(64);
        }
        __syncthreads();
        __threadfence();
        if (t < 8) sx[t] = 0.f;
        __syncthreads();
        if (t < 8 * MCAND) {
            int i = t / MCAND, m = t - i * MCAND;
            atomicAdd(&sx[i], __ldcg(&g_attn[m]) * __ldcg(&g_C[m * D + rb + i]));
        }
        __syncthreads();
        float acc[8];
#pragma unroll
        for (int k = 0; k < 8; ++k) acc[k] = 0.f;
#pragma unroll
        for (int i = 0; i < 8; ++i) {
            float x = sx[i];
            const float* wr2 = Wm + (size_t)(rb + i) * D;
#pragma unroll
            for (int k = 0; k < 8; ++k) acc[k] += x * wr2[t + 256 * k];
        }
#pragma unroll
        for (int k = 0; k < 8; ++k) atomicAdd(&g_spre[t + 256 * k], acc[k]);
        __threadfence();
        __syncthreads();
        if (t == 0) smlast = atomicAdd(&cnt_w, 1);
        __syncthreads();
        if (smlast == WM_BLOCKS - 1) {
            __threadfence();
            float g = g_scalars[0];
#pragma unroll
            for (int k = 0; k < 8; ++k) {
                int j = t + 256 * k;
                out[j] = g * tanhf(__ldcg(&g_spre[j]) + bm[j]);
                g_spre[j] = 0.f;
                g_qv_pre[j] = 0.f;
                g_gate_pre[j] = 0.f;
                g_v[j] = 0.f;
            }
            if (t == 0) {
                atomicExch(&cnt_w, 0);
                atomicExch(&g_flag, 0);
            }
        }
    }
}

// ======================= launch =======================
extern "C" void kernel_launch(void* const* d_in, const int* in_sizes, int n_in,
                              void* d_out, int out_size) {
    const float* z     = (const float*)d_in[0];
    const float* h     = (const float*)d_in[1];
    const float* mem   = (const float*)d_in[2];
    const float* noise = (const float*)d_in[3];
    const float* Wq    = (const float*)d_in[4];
    const float* bq    = (const float*)d_in[5];
    const float* Wc    = (const float*)d_in[6];
    const float* bc    = (const float*)d_in[7];
    const float* ws    = (const float*)d_in[8];
    const float* bs    = (const float*)d_in[9];
    const float* Wm    = (const float*)d_in[10];
    const float* bm    = (const float*)d_in[11];
    const float* Wg1   = (const float*)d_in[12];
    const float* bg1   = (const float*)d_in[13];
    const float* wg2   = (const float*)d_in[14];
    const float* bg2   = (const float*)d_in[15];
    float* out = (float*)d_out;

    k1_bulk<<<K1_GRID, 256>>>(z, h, mem, Wq, Wg1, noise);
    k2_mid<<<K2_GRID, 256>>>(mem, Wc, bq, ws, bs, bc, bg1, wg2, bg2);
    k3_fin<<<K3_GRID, 256>>>(Wm, bm, out);
}

// round 7
// speedup vs baseline: 1.6226x; 1.1621x over previous
#include <cuda_runtime.h>
#include <math.h>

#define D       2048
#define NROWS   65536
#define NDREAMS 4
#define KMEM    8
#define MCAND   12

#define MV_BLOCKS 128            // Wq + Wg1: 64 blocks each, 64 rows per block
#define SIMS_BLOCKS 1024
#define K1_GRID (MV_BLOCKS + NDREAMS + SIMS_BLOCKS)

#define WC_BLOCKS 256            // 256 blocks x 8 warps = 2048 full rows
#define K2_GRID (WC_BLOCKS + 2)  // + select/gather block + scalars block

#define WM_BLOCKS 256            // 256 blocks x 8 rows
#define K3_GRID WM_BLOCKS

// ---------------- scratch (zero-initialized at module load; reset each launch) ----
__device__ float g_qv_pre[D];        // reset by K3 out-block
__device__ float g_gate_pre[D];      // reset by K3 out-block
__device__ float g_spre[D];          // reset by K3 out-block
__device__ float g_logits[MCAND];    // reset by K3 out-block
__device__ float g_C[MCAND * D];
__device__ float g_scalars[2];       // [0]=gate, [1]=cb
__device__ float g_pool_v[SIMS_BLOCKS * KMEM];
__device__ int   g_pool_i[SIMS_BLOCKS * KMEM];
__device__ int   g_flag;             // gather done; reset by K3 out-block
__device__ int   cnt_w;              // Wm completion; reset by K3 out-block

__device__ __forceinline__ float warp_sum(float v) {
#pragma unroll
    for (int off = 16; off; off >>= 1) v += __shfl_down_sync(0xFFFFFFFFu, v, off);
    return v;
}

// ======================= K1: bulk (matvecs + dreams + sims) ==================
__global__ __launch_bounds__(256, 4) void k1_bulk(const float* __restrict__ z,
                                                  const float* __restrict__ h,
                                                  const float* __restrict__ mem,
                                                  const float* __restrict__ Wq,
                                                  const float* __restrict__ Wg1,
                                                  const float* __restrict__ noise) {
    __shared__ float zsh[D];
    __shared__ float sscore[64];
    int b = blockIdx.x, t = threadIdx.x;
    int warp = t >> 5, lane = t & 31;

    if (b < MV_BLOCKS) {
        const float* W   = (b < 64) ? Wq : Wg1;
        float*       dst = (b < 64) ? g_qv_pre : g_gate_pre;
        int rb = (b & 63) * 64;
        float acc[8];
#pragma unroll
        for (int k = 0; k < 8; ++k) acc[k] = 0.f;
        for (int i = 0; i < 64; ++i) {
            int row = rb + i;
            float x = (row < D) ? z[row] : h[row - D];
            const float* wr = W + (size_t)row * D;
#pragma unroll
            for (int k = 0; k < 8; ++k) acc[k] += x * wr[t + 256 * k];
        }
#pragma unroll
        for (int k = 0; k < 8; ++k) atomicAdd(&dst[t + 256 * k], acc[k]);
    } else if (b < MV_BLOCKS + NDREAMS) {
        __shared__ float red[8];
        int dm = b - MV_BLOCKS;
        float ss = 0.f;
#pragma unroll
        for (int k = 0; k < 8; ++k) {
            int j = t + 256 * k;
            float v = 0.7f * noise[dm * D + j] + 0.3f * z[j];
            zsh[j] = v;
            ss += v * v;
        }
        ss = warp_sum(ss);
        if (lane == 0) red[warp] = ss;
        __syncthreads();
        if (t == 0) {
            float s = 0.f;
#pragma unroll
            for (int w = 0; w < 8; ++w) s += red[w];
            red[0] = s;
        }
        __syncthreads();
        float inv = 1.0f / fmaxf(sqrtf(red[0]), 1e-12f);
#pragma unroll
        for (int k = 0; k < 8; ++k) {
            int j = t + 256 * k;
            g_C[(KMEM + dm) * D + j] = zsh[j] * inv;
        }
    } else {
        int sb = b - MV_BLOCKS - NDREAMS;            // 0..1023
#pragma unroll
        for (int k = 0; k < 8; ++k) zsh[t + 256 * k] = z[t + 256 * k];
        __syncthreads();
        const float4* z4 = (const float4*)zsh;
        int wg = sb * 8 + warp;                      // 0..8191
#pragma unroll 1
        for (int p = 0; p < 4; ++p) {
            int rA = 2 * wg + 16384 * p;
            const float4* A4 = (const float4*)(mem + (size_t)rA * D);
            const float4* B4 = (const float4*)(mem + (size_t)(rA + 1) * D);
            float dA0 = 0, dA1 = 0, nA0 = 0, nA1 = 0;
            float dB0 = 0, dB1 = 0, nB0 = 0, nB1 = 0;
#pragma unroll
            for (int it = 0; it < 16; ++it) {
                float4 va = __ldcs(&A4[lane + 32 * it]);
                float4 vb = __ldcs(&B4[lane + 32 * it]);
                float4 zz = z4[lane + 32 * it];
                dA0 += va.x * zz.x + va.y * zz.y;
                dA1 += va.z * zz.z + va.w * zz.w;
                nA0 += va.x * va.x + va.y * va.y;
                nA1 += va.z * va.z + va.w * va.w;
                dB0 += vb.x * zz.x + vb.y * zz.y;
                dB1 += vb.z * zz.z + vb.w * zz.w;
                nB0 += vb.x * vb.x + vb.y * vb.y;
                nB1 += vb.z * vb.z + vb.w * vb.w;
            }
            float dA = warp_sum(dA0 + dA1);
            float nA = warp_sum(nA0 + nA1);
            float dB = warp_sum(dB0 + dB1);
            float nB = warp_sum(nB0 + nB1);
            if (lane == 0) {
                sscore[warp * 8 + p * 2]     = dA * rsqrtf(nA);
                sscore[warp * 8 + p * 2 + 1] = dB * rsqrtf(nB);
            }
        }
        __syncthreads();

        if (warp == 0) {
            int s0 = lane, s1 = lane + 32;
            float v0 = sscore[s0], v1 = sscore[s1];
            int r0 = 2 * (sb * 8 + (s0 >> 3)) + 16384 * ((s0 & 7) >> 1) + (s0 & 1);
            int r1 = 2 * (sb * 8 + (s1 >> 3)) + 16384 * ((s1 & 7) >> 1) + (s1 & 1);
            if (v1 > v0) { float tv = v0; v0 = v1; v1 = tv; int ti = r0; r0 = r1; r1 = ti; }
#pragma unroll 1
            for (int p = 0; p < KMEM; ++p) {
                float best = v0; int bl = lane;
#pragma unroll
                for (int off = 16; off; off >>= 1) {
                    float ov = __shfl_down_sync(0xFFFFFFFFu, best, off);
                    int obl  = __shfl_down_sync(0xFFFFFFFFu, bl, off);
                    if (ov > best) { best = ov; bl = obl; }
                }
                int wl = __shfl_sync(0xFFFFFFFFu, bl, 0);
                float wv = __shfl_sync(0xFFFFFFFFu, v0, wl);
                int  wr = __shfl_sync(0xFFFFFFFFu, r0, wl);
                if (lane == 0) { g_pool_v[sb * 8 + p] = wv; g_pool_i[sb * 8 + p] = wr; }
                if (lane == wl) { v0 = v1; r0 = r1; v1 = -INFINITY; }
            }
        }
    }
}

// ======================= K2: Wc full-row matvec + fused logits + select/gather =
// blocks [0,256)   : warp w computes v[b*8+w] = Wc row . qws fully, then the
//                    block adds its 12 logit partials (needs C -> poll flag).
// block 256        : final top-8 from pool -> gather protos -> set flag
// block 257        : scalars (cb, gate)
__global__ __launch_bounds__(256) void k2_mid(const float* __restrict__ mem,
                                              const float* __restrict__ Wc,
                                              const float* __restrict__ bq,
                                              const float* __restrict__ ws,
                                              const float* __restrict__ bs,
                                              const float* __restrict__ bc,
                                              const float* __restrict__ bg1,
                                              const float* __restrict__ wg2,
                                              const float* __restrict__ bg2) {
    __shared__ float qsh[D];
    __shared__ float vsh[8];
    int b = blockIdx.x, t = threadIdx.x;
    int warp = t >> 5, lane = t & 31;

    if (b < WC_BLOCKS) {
#pragma unroll
        for (int k = 0; k < 8; ++k) {
            int j = t + 256 * k;
            qsh[j] = tanhf(g_qv_pre[j] + bq[j]) * ws[j];
        }
        __syncthreads();
        int row = b * 8 + warp;               // 0..2047
        const float4* wr = (const float4*)(Wc + (size_t)row * D);
        const float4* q4 = (const float4*)qsh;
        float a0 = 0, a1 = 0, a2 = 0, a3 = 0;
#pragma unroll
        for (int it = 0; it < 16; ++it) {
            float4 wv = __ldcs(&wr[lane + 32 * it]);
            float4 qv = q4[lane + 32 * it];
            a0 += wv.x * qv.x; a1 += wv.y * qv.y; a2 += wv.z * qv.z; a3 += wv.w * qv.w;
        }
        float s = warp_sum((a0 + a1) + (a2 + a3));
        if (lane == 0) vsh[warp] = s;
        // wait for gather (normally long done by now)
        if (t == 0) {
            volatile int* vf = &g_flag;
            while (*vf == 0) __nanosleep(64);
        }
        __syncthreads();
        __threadfence();
        if (t < MCAND) {
            int rb = b * 8;
            float p = 0.f;
#pragma unroll
            for (int i = 0; i < 8; ++i) p += vsh[i] * __ldcg(&g_C[t * D + rb + i]);
            atomicAdd(&g_logits[t], p);
        }
    } else if (b == WC_BLOCKS) {
        // ---- final top-8 over 8192-entry pool, then gather protos, set flag ----
        __shared__ float pv2[64];
        __shared__ int   pi2[64];
        __shared__ int   sidx[KMEM];
        float bv[KMEM]; int bi[KMEM];
#pragma unroll
        for (int q = 0; q < KMEM; ++q) { bv[q] = -INFINITY; bi[q] = 0; }
#pragma unroll 1
        for (int f = 0; f < 32; ++f) {
            int e = t + 256 * f;
            float s = g_pool_v[e];
            if (s > bv[KMEM - 1]) {
                bv[KMEM - 1] = s; bi[KMEM - 1] = g_pool_i[e];
#pragma unroll
                for (int q = KMEM - 1; q > 0; --q) {
                    if (bv[q] > bv[q - 1]) {
                        float tv = bv[q - 1]; int ti = bi[q - 1];
                        bv[q - 1] = bv[q]; bi[q - 1] = bi[q];
                        bv[q] = tv; bi[q] = ti;
                    }
                }
            }
        }
#pragma unroll 1
        for (int p = 0; p < KMEM; ++p) {
            float v = bv[0]; int id = bi[0]; int ln = lane;
#pragma unroll
            for (int off = 16; off; off >>= 1) {
                float ov = __shfl_down_sync(0xFFFFFFFFu, v, off);
                int oid  = __shfl_down_sync(0xFFFFFFFFu, id, off);
                int oln  = __shfl_down_sync(0xFFFFFFFFu, ln, off);
                if (ov > v) { v = ov; id = oid; ln = oln; }
            }
            int wln = __shfl_sync(0xFFFFFFFFu, ln, 0);
            if (lane == 0) { pv2[warp * 8 + p] = v; pi2[warp * 8 + p] = id; }
            if (lane == wln) {
#pragma unroll
                for (int q = 0; q < KMEM - 1; ++q) { bv[q] = bv[q + 1]; bi[q] = bi[q + 1]; }
                bv[KMEM - 1] = -INFINITY;
            }
        }
        __syncthreads();
        if (warp == 0) {
            float v0 = pv2[lane], v1 = pv2[lane + 32];
            int   i0 = pi2[lane], i1 = pi2[lane + 32];
            if (v1 > v0) { float tv = v0; v0 = v1; v1 = tv; int ti = i0; i0 = i1; i1 = ti; }
#pragma unroll 1
            for (int p = 0; p < KMEM; ++p) {
                float best = v0; int bl = lane;
#pragma unroll
                for (int off = 16; off; off >>= 1) {
                    float ov = __shfl_down_sync(0xFFFFFFFFu, best, off);
                    int obl  = __shfl_down_sync(0xFFFFFFFFu, bl, off);
                    if (ov > best) { best = ov; bl = obl; }
                }
                int wl = __shfl_sync(0xFFFFFFFFu, bl, 0);
                int wi = __shfl_sync(0xFFFFFFFFu, i0, wl);
                if (lane == 0) sidx[p] = wi;
                if (lane == wl) { v0 = v1; i0 = i1; v1 = -INFINITY; }
            }
        }
        __syncthreads();
#pragma unroll 1
        for (int m = 0; m < KMEM; ++m) {
            int r = sidx[m];
            const float4* src = (const float4*)(mem + (size_t)r * D);
            float4* dst = (float4*)(g_C + m * D);
#pragma unroll
            for (int k = 0; k < 2; ++k) dst[t + 256 * k] = src[t + 256 * k];
        }
        __syncthreads();
        if (t == 0) {
            __threadfence();
            *(volatile int*)&g_flag = 1;
        }
    } else {
        __shared__ float scb[8], sgp[8];
        float cbp = 0.f, gp = 0.f;
#pragma unroll
        for (int k = 0; k < 8; ++k) {
            int j = t + 256 * k;
            cbp += bc[j] * tanhf(g_qv_pre[j] + bq[j]) * ws[j];
            gp  += tanhf(g_gate_pre[j] + bg1[j]) * wg2[j];
        }
        cbp = warp_sum(cbp);
        gp  = warp_sum(gp);
        if (lane == 0) { scb[warp] = cbp; sgp[warp] = gp; }
        __syncthreads();
        if (t == 0) {
            float c = 0.f, g = 0.f;
#pragma unroll
            for (int w2 = 0; w2 < 8; ++w2) { c += scb[w2]; g += sgp[w2]; }
            g_scalars[1] = c + bs[0];
            g_scalars[0] = 1.0f / (1.0f + expf(-(g + bg2[0])));
        }
    }
}

// ======================= K3: per-block local softmax + Wm + out ===============
// every block: softmax(g_logits + cb) locally -> x slice from C -> stream 8 Wm
// rows -> atomicAdd g_spre. Counter-elected last block writes out + resets.
__global__ __launch_bounds__(256) void k3_fin(const float* __restrict__ Wm,
                                              const float* __restrict__ bm,
                                              float* __restrict__ out) {
    __shared__ float sattn[MCAND];
    __shared__ float sx[8];
    __shared__ int   smlast;
    int b = blockIdx.x, t = threadIdx.x;
    int rb = b * 8;

    if (t == 0) {
        float lg[MCAND]; float mx = -INFINITY;
        float cb = g_scalars[1];
#pragma unroll
        for (int m = 0; m < MCAND; ++m) {
            lg[m] = g_logits[m] + cb;
            mx = fmaxf(mx, lg[m]);
        }
        float den = 0.f;
#pragma unroll
        for (int m = 0; m < MCAND; ++m) { lg[m] = expf(lg[m] - mx); den += lg[m]; }
        float inv = 1.0f / den;
#pragma unroll
        for (int m = 0; m < MCAND; ++m) sattn[m] = lg[m] * inv;
    }
    __syncthreads();
    if (t < 8) {
        float x = 0.f;
#pragma unroll
        for (int m = 0; m < MCAND; ++m) x += sattn[m] * g_C[m * D + rb + t];
        sx[t] = x;
    }
    __syncthreads();

    float acc[8];
#pragma unroll
    for (int k = 0; k < 8; ++k) acc[k] = 0.f;
#pragma unroll
    for (int i = 0; i < 8; ++i) {
        float x = sx[i];
        const float* wr = Wm + (size_t)(rb + i) * D;
#pragma unroll
        for (int k = 0; k < 8; ++k) acc[k] += x * __ldcs(&wr[t + 256 * k]);
    }
#pragma unroll
    for (int k = 0; k < 8; ++k) atomicAdd(&g_spre[t + 256 * k], acc[k]);
    __threadfence();
    __syncthreads();
    if (t == 0) smlast = atomicAdd(&cnt_w, 1);
    __syncthreads();
    if (smlast == WM_BLOCKS - 1) {
        __threadfence();
        float g = g_scalars[0];
#pragma unroll
        for (int k = 0; k < 8; ++k) {
            int j = t + 256 * k;
            out[j] = g * tanhf(__ldcg(&g_spre[j]) + bm[j]);
            g_spre[j] = 0.f;
            g_qv_pre[j] = 0.f;
            g_gate_pre[j] = 0.f;
        }
        if (t < MCAND) g_logits[t] = 0.f;
        if (t == 0) {
            atomicExch(&cnt_w, 0);
            atomicExch(&g_flag, 0);
        }
    }
}

// ======================= launch =======================
extern "C" void kernel_launch(void* const* d_in, const int* in_sizes, int n_in,
                              void* d_out, int out_size) {
    const float* z     = (const float*)d_in[0];
    const float* h     = (const float*)d_in[1];
    const float* mem   = (const float*)d_in[2];
    const float* noise = (const float*)d_in[3];
    const float* Wq    = (const float*)d_in[4];
    const float* bq    = (const float*)d_in[5];
    const float* Wc    = (const float*)d_in[6];
    const float* bc    = (const float*)d_in[7];
    const float* ws    = (const float*)d_in[8];
    const float* bs    = (const float*)d_in[9];
    const float* Wm    = (const float*)d_in[10];
    const float* bm    = (const float*)d_in[11];
    const float* Wg1   = (const float*)d_in[12];
    const float* bg1   = (const float*)d_in[13];
    const float* wg2   = (const float*)d_in[14];
    const float* bg2   = (const float*)d_in[15];
    float* out = (float*)d_out;

    k1_bulk<<<K1_GRID, 256>>>(z, h, mem, Wq, Wg1, noise);
    k2_mid<<<K2_GRID, 256>>>(mem, Wc, bq, ws, bs, bc, bg1, wg2, bg2);
    k3_fin<<<K3_GRID, 256>>>(Wm, bm, out);
}

// round 8
// speedup vs baseline: 1.7403x; 1.0725x over previous
#include <cuda_runtime.h>
#include <math.h>

#define D       2048
#define NROWS   65536
#define NDREAMS 4
#define KMEM    8
#define MCAND   12

#define MV_BLOCKS 128            // Wq + Wg1: 64 blocks each, 64 rows per block
#define SIMS_BLOCKS 1024
#define WC_BLOCKS 256            // 256 blocks x 8 warps = 2048 full rows
// k1 grid layout: [MV][dreams][sims][Wc][scalars]  (Wc/scalars tail-scheduled)
#define K1_WC_BASE  (MV_BLOCKS + NDREAMS + SIMS_BLOCKS)
#define K1_GRID     (K1_WC_BASE + WC_BLOCKS + 1)

#define WM_BLOCKS 256            // 256 blocks x 8 rows
#define K3_GRID WM_BLOCKS

// ---------------- scratch (zero-initialized at module load; reset each launch) ----
__device__ float g_qv_pre[D];        // reset by K3 out-block
__device__ float g_gate_pre[D];      // reset by K3 out-block
__device__ float g_spre[D];          // reset by K3 out-block
__device__ float g_v[D];             // fully overwritten each launch
__device__ float g_C[MCAND * D];     // fully overwritten each launch
__device__ float g_attn[MCAND];      // fully overwritten each launch
__device__ float g_scalars[2];       // [0]=gate, [1]=cb ; overwritten
__device__ float g_pool_v[SIMS_BLOCKS * KMEM];
__device__ int   g_pool_i[SIMS_BLOCKS * KMEM];
__device__ int   cnt_mv;             // Wq+Wg1 completion; reset by K3 out-block
__device__ int   cnt_w;              // Wm completion;     reset by K3 out-block

__device__ __forceinline__ float warp_sum(float v) {
#pragma unroll
    for (int off = 16; off; off >>= 1) v += __shfl_down_sync(0xFFFFFFFFu, v, off);
    return v;
}

// ======================= K1: bulk =============================================
// [0,128)          : Wq / Wg1 matvec partials (atomicAdd) + cnt_mv bump
// [128,132)        : dreams -> g_C rows 8..11
// [132,1156)       : cosine scores; block top-8 -> pool
// [1156,1412)      : Wc full-row matvec -> g_v   (poll cnt_mv; tail wave)
// 1412             : scalars (cb, gate)          (poll cnt_mv)
__global__ __launch_bounds__(256, 4) void k1_bulk(const float* __restrict__ z,
                                                  const float* __restrict__ h,
                                                  const float* __restrict__ mem,
                                                  const float* __restrict__ Wq,
                                                  const float* __restrict__ Wg1,
                                                  const float* __restrict__ Wc,
                                                  const float* __restrict__ noise,
                                                  const float* __restrict__ bq,
                                                  const float* __restrict__ ws,
                                                  const float* __restrict__ bs,
                                                  const float* __restrict__ bc,
                                                  const float* __restrict__ bg1,
                                                  const float* __restrict__ wg2,
                                                  const float* __restrict__ bg2) {
    __shared__ float zsh[D];
    __shared__ float sscore[64];
    int b = blockIdx.x, t = threadIdx.x;
    int warp = t >> 5, lane = t & 31;

    if (b < MV_BLOCKS) {
        const float* W   = (b < 64) ? Wq : Wg1;
        float*       dst = (b < 64) ? g_qv_pre : g_gate_pre;
        int rb = (b & 63) * 64;
        float acc[8];
#pragma unroll
        for (int k = 0; k < 8; ++k) acc[k] = 0.f;
        for (int i = 0; i < 64; ++i) {
            int row = rb + i;
            float x = (row < D) ? z[row] : h[row - D];
            const float* wr = W + (size_t)row * D;
#pragma unroll
            for (int k = 0; k < 8; ++k) acc[k] += x * wr[t + 256 * k];
        }
#pragma unroll
        for (int k = 0; k < 8; ++k) atomicAdd(&dst[t + 256 * k], acc[k]);
        __threadfence();
        __syncthreads();
        if (t == 0) atomicAdd(&cnt_mv, 1);
    } else if (b < MV_BLOCKS + NDREAMS) {
        __shared__ float red[8];
        int dm = b - MV_BLOCKS;
        float ss = 0.f;
#pragma unroll
        for (int k = 0; k < 8; ++k) {
            int j = t + 256 * k;
            float v = 0.7f * noise[dm * D + j] + 0.3f * z[j];
            zsh[j] = v;
            ss += v * v;
        }
        ss = warp_sum(ss);
        if (lane == 0) red[warp] = ss;
        __syncthreads();
        if (t == 0) {
            float s = 0.f;
#pragma unroll
            for (int w = 0; w < 8; ++w) s += red[w];
            red[0] = s;
        }
        __syncthreads();
        float inv = 1.0f / fmaxf(sqrtf(red[0]), 1e-12f);
#pragma unroll
        for (int k = 0; k < 8; ++k) {
            int j = t + 256 * k;
            g_C[(KMEM + dm) * D + j] = zsh[j] * inv;
        }
    } else if (b < K1_WC_BASE) {
        int sb = b - MV_BLOCKS - NDREAMS;            // 0..1023
#pragma unroll
        for (int k = 0; k < 8; ++k) zsh[t + 256 * k] = z[t + 256 * k];
        __syncthreads();
        const float4* z4 = (const float4*)zsh;
        int wg = sb * 8 + warp;                      // 0..8191
#pragma unroll 1
        for (int p = 0; p < 4; ++p) {
            int rA = 2 * wg + 16384 * p;
            const float4* A4 = (const float4*)(mem + (size_t)rA * D);
            const float4* B4 = (const float4*)(mem + (size_t)(rA + 1) * D);
            float dA0 = 0, dA1 = 0, nA0 = 0, nA1 = 0;
            float dB0 = 0, dB1 = 0, nB0 = 0, nB1 = 0;
#pragma unroll
            for (int it = 0; it < 16; ++it) {
                float4 va = __ldcs(&A4[lane + 32 * it]);
                float4 vb = __ldcs(&B4[lane + 32 * it]);
                float4 zz = z4[lane + 32 * it];
                dA0 += va.x * zz.x + va.y * zz.y;
                dA1 += va.z * zz.z + va.w * zz.w;
                nA0 += va.x * va.x + va.y * va.y;
                nA1 += va.z * va.z + va.w * va.w;
                dB0 += vb.x * zz.x + vb.y * zz.y;
                dB1 += vb.z * zz.z + vb.w * zz.w;
                nB0 += vb.x * vb.x + vb.y * vb.y;
                nB1 += vb.z * vb.z + vb.w * vb.w;
            }
            float dA = warp_sum(dA0 + dA1);
            float nA = warp_sum(nA0 + nA1);
            float dB = warp_sum(dB0 + dB1);
            float nB = warp_sum(nB0 + nB1);
            if (lane == 0) {
                sscore[warp * 8 + p * 2]     = dA * rsqrtf(nA);
                sscore[warp * 8 + p * 2 + 1] = dB * rsqrtf(nB);
            }
        }
        __syncthreads();

        if (warp == 0) {
            int s0 = lane, s1 = lane + 32;
            float v0 = sscore[s0], v1 = sscore[s1];
            int r0 = 2 * (sb * 8 + (s0 >> 3)) + 16384 * ((s0 & 7) >> 1) + (s0 & 1);
            int r1 = 2 * (sb * 8 + (s1 >> 3)) + 16384 * ((s1 & 7) >> 1) + (s1 & 1);
            if (v1 > v0) { float tv = v0; v0 = v1; v1 = tv; int ti = r0; r0 = r1; r1 = ti; }
#pragma unroll 1
            for (int p = 0; p < KMEM; ++p) {
                float best = v0; int bl = lane;
#pragma unroll
                for (int off = 16; off; off >>= 1) {
                    float ov = __shfl_down_sync(0xFFFFFFFFu, best, off);
                    int obl  = __shfl_down_sync(0xFFFFFFFFu, bl, off);
                    if (ov > best) { best = ov; bl = obl; }
                }
                int wl = __shfl_sync(0xFFFFFFFFu, bl, 0);
                float wv = __shfl_sync(0xFFFFFFFFu, v0, wl);
                int  wr = __shfl_sync(0xFFFFFFFFu, r0, wl);
                if (lane == 0) { g_pool_v[sb * 8 + p] = wv; g_pool_i[sb * 8 + p] = wr; }
                if (lane == wl) { v0 = v1; r0 = r1; v1 = -INFINITY; }
            }
        }
    } else if (b < K1_WC_BASE + WC_BLOCKS) {
        // ---- Wc full-row matvec (tail wave; Wq long done -> poll is instant) ----
        int wb = b - K1_WC_BASE;                     // 0..255
        if (t == 0) {
            volatile int* c = &cnt_mv;
            while (*c < MV_BLOCKS) __nanosleep(32);
        }
        __syncthreads();
        __threadfence();
#pragma unroll
        for (int k = 0; k < 8; ++k) {
            int j = t + 256 * k;
            zsh[j] = tanhf(__ldcg(&g_qv_pre[j]) + bq[j]) * ws[j];
        }
        __syncthreads();
        int row = wb * 8 + warp;                     // 0..2047
        const float4* wr = (const float4*)(Wc + (size_t)row * D);
        const float4* q4 = (const float4*)zsh;
        float a0 = 0, a1 = 0, a2 = 0, a3 = 0;
#pragma unroll
        for (int it = 0; it < 16; ++it) {
            float4 wv = __ldcs(&wr[lane + 32 * it]);
            float4 qv = q4[lane + 32 * it];
            a0 += wv.x * qv.x; a1 += wv.y * qv.y; a2 += wv.z * qv.z; a3 += wv.w * qv.w;
        }
        float s = warp_sum((a0 + a1) + (a2 + a3));
        if (lane == 0) g_v[row] = s;
    } else {
        // ---- scalars ----
        __shared__ float scb[8], sgp[8];
        if (t == 0) {
            volatile int* c = &cnt_mv;
            while (*c < MV_BLOCKS) __nanosleep(32);
        }
        __syncthreads();
        __threadfence();
        float cbp = 0.f, gp = 0.f;
#pragma unroll
        for (int k = 0; k < 8; ++k) {
            int j = t + 256 * k;
            cbp += bc[j] * tanhf(__ldcg(&g_qv_pre[j]) + bq[j]) * ws[j];
            gp  += tanhf(__ldcg(&g_gate_pre[j]) + bg1[j]) * wg2[j];
        }
        cbp = warp_sum(cbp);
        gp  = warp_sum(gp);
        if (lane == 0) { scb[warp] = cbp; sgp[warp] = gp; }
        __syncthreads();
        if (t == 0) {
            float c = 0.f, g = 0.f;
#pragma unroll
            for (int w2 = 0; w2 < 8; ++w2) { c += scb[w2]; g += sgp[w2]; }
            g_scalars[1] = c + bs[0];
            g_scalars[0] = 1.0f / (1.0f + expf(-(g + bg2[0])));
        }
    }
}

// ======================= K2: select + gather + logits + softmax (1 block) =====
__global__ __launch_bounds__(1024) void k2_sel(const float* __restrict__ mem) {
    __shared__ float pv2[256];
    __shared__ int   pi2[256];
    __shared__ int   sidx[KMEM];
    __shared__ float slog[MCAND];
    int t = threadIdx.x, lane = t & 31, warp = t >> 5;

    // per-thread top-8 over 8 pool entries (pool = 8192)
    float bv[KMEM]; int bi[KMEM];
#pragma unroll
    for (int q = 0; q < KMEM; ++q) { bv[q] = -INFINITY; bi[q] = 0; }
#pragma unroll 1
    for (int f = 0; f < 8; ++f) {
        int e = t + 1024 * f;
        float s = g_pool_v[e];
        if (s > bv[KMEM - 1]) {
            bv[KMEM - 1] = s; bi[KMEM - 1] = g_pool_i[e];
#pragma unroll
            for (int q = KMEM - 1; q > 0; --q) {
                if (bv[q] > bv[q - 1]) {
                    float tv = bv[q - 1]; int ti = bi[q - 1];
                    bv[q - 1] = bv[q]; bi[q - 1] = bi[q];
                    bv[q] = tv; bi[q] = ti;
                }
            }
        }
    }
    // warp merge: 32 sorted lists -> warp top-8 -> pool of 32*8=256
#pragma unroll 1
    for (int p = 0; p < KMEM; ++p) {
        float v = bv[0]; int id = bi[0]; int ln = lane;
#pragma unroll
        for (int off = 16; off; off >>= 1) {
            float ov = __shfl_down_sync(0xFFFFFFFFu, v, off);
            int oid  = __shfl_down_sync(0xFFFFFFFFu, id, off);
            int oln  = __shfl_down_sync(0xFFFFFFFFu, ln, off);
            if (ov > v) { v = ov; id = oid; ln = oln; }
        }
        int wln = __shfl_sync(0xFFFFFFFFu, ln, 0);
        if (lane == 0) { pv2[warp * 8 + p] = v; pi2[warp * 8 + p] = id; }
        if (lane == wln) {
#pragma unroll
            for (int q = 0; q < KMEM - 1; ++q) { bv[q] = bv[q + 1]; bi[q] = bi[q + 1]; }
            bv[KMEM - 1] = -INFINITY;
        }
    }
    __syncthreads();
    // warp 0: 8 argmax passes over the 256-entry pool
    if (warp == 0) {
#pragma unroll 1
        for (int p = 0; p < KMEM; ++p) {
            float best = -INFINITY; int bslot = lane;
#pragma unroll
            for (int e = 0; e < 8; ++e) {
                int slot = lane + 32 * e;
                float v = pv2[slot];
                if (v > best) { best = v; bslot = slot; }
            }
#pragma unroll
            for (int off = 16; off; off >>= 1) {
                float ov = __shfl_down_sync(0xFFFFFFFFu, best, off);
                int osl  = __shfl_down_sync(0xFFFFFFFFu, bslot, off);
                if (ov > best) { best = ov; bslot = osl; }
            }
            if (lane == 0) { sidx[p] = pi2[bslot]; pv2[bslot] = -INFINITY; }
            __syncwarp();
        }
    }
    __syncthreads();
    // gather 8 protos (4096 float4 total) with 1024 threads
#pragma unroll 1
    for (int idx = t; idx < KMEM * (D / 4); idx += 1024) {
        int m = idx >> 9, off = idx & 511;
        ((float4*)(g_C + m * D))[off] =
            ((const float4*)(mem + (size_t)sidx[m] * D))[off];
    }
    __syncthreads();
    // logits: warp m computes dot(C[m], v)
    if (warp < MCAND) {
        float a = 0.f;
        for (int j = lane; j < D; j += 32) a += g_C[warp * D + j] * g_v[j];
        a = warp_sum(a);
        if (lane == 0) slog[warp] = a;
    }
    __syncthreads();
    if (t == 0) {
        float lg[MCAND]; float mx = -INFINITY;
        float cb = g_scalars[1];
#pragma unroll
        for (int m = 0; m < MCAND; ++m) {
            lg[m] = slog[m] + cb;
            mx = fmaxf(mx, lg[m]);
        }
        float den = 0.f;
#pragma unroll
        for (int m = 0; m < MCAND; ++m) { lg[m] = expf(lg[m] - mx); den += lg[m]; }
        float inv = 1.0f / den;
#pragma unroll
        for (int m = 0; m < MCAND; ++m) g_attn[m] = lg[m] * inv;
    }
}

// ======================= K3: Wm matvec + out ==================================
__global__ __launch_bounds__(256) void k3_fin(const float* __restrict__ Wm,
                                              const float* __restrict__ bm,
                                              float* __restrict__ out) {
    __shared__ float sattn[MCAND];
    __shared__ float sx[8];
    __shared__ int   smlast;
    int b = blockIdx.x, t = threadIdx.x;
    int rb = b * 8;

    if (t < MCAND) sattn[t] = g_attn[t];
    __syncthreads();
    if (t < 8) {
        float x = 0.f;
#pragma unroll
        for (int m = 0; m < MCAND; ++m) x += sattn[m] * g_C[m * D + rb + t];
        sx[t] = x;
    }
    __syncthreads();

    float acc[8];
#pragma unroll
    for (int k = 0; k < 8; ++k) acc[k] = 0.f;
#pragma unroll
    for (int i = 0; i < 8; ++i) {
        float x = sx[i];
        const float* wr = Wm + (size_t)(rb + i) * D;
#pragma unroll
        for (int k = 0; k < 8; ++k) acc[k] += x * __ldcs(&wr[t + 256 * k]);
    }
#pragma unroll
    for (int k = 0; k < 8; ++k) atomicAdd(&g_spre[t + 256 * k], acc[k]);
    __threadfence();
    __syncthreads();
    if (t == 0) smlast = atomicAdd(&cnt_w, 1);
    __syncthreads();
    if (smlast == WM_BLOCKS - 1) {
        __threadfence();
        float g = g_scalars[0];
#pragma unroll
        for (int k = 0; k < 8; ++k) {
            int j = t + 256 * k;
            out[j] = g * tanhf(__ldcg(&g_spre[j]) + bm[j]);
            g_spre[j] = 0.f;
            g_qv_pre[j] = 0.f;
            g_gate_pre[j] = 0.f;
        }
        if (t == 0) {
            atomicExch(&cnt_w, 0);
            atomicExch(&cnt_mv, 0);
        }
    }
}

// ======================= launch =======================
extern "C" void kernel_launch(void* const* d_in, const int* in_sizes, int n_in,
                              void* d_out, int out_size) {
    const float* z     = (const float*)d_in[0];
    const float* h     = (const float*)d_in[1];
    const float* mem   = (const float*)d_in[2];
    const float* noise = (const float*)d_in[3];
    const float* Wq    = (const float*)d_in[4];
    const float* bq    = (const float*)d_in[5];
    const float* Wc    = (const float*)d_in[6];
    const float* bc    = (const float*)d_in[7];
    const float* ws    = (const float*)d_in[8];
    const float* bs    = (const float*)d_in[9];
    const float* Wm    = (const float*)d_in[10];
    const float* bm    = (const float*)d_in[11];
    const float* Wg1   = (const float*)d_in[12];
    const float* bg1   = (const float*)d_in[13];
    const float* wg2   = (const float*)d_in[14];
    const float* bg2   = (const float*)d_in[15];
    float* out = (float*)d_out;

    k1_bulk<<<K1_GRID, 256>>>(z, h, mem, Wq, Wg1, Wc, noise,
                              bq, ws, bs, bc, bg1, wg2, bg2);
    k2_sel<<<1, 1024>>>(mem);
    k3_fin<<<K3_GRID, 256>>>(Wm, bm, out);
}